// round 4
// baseline (speedup 1.0000x reference)
#include <cuda_runtime.h>
#include <cstdint>

// PatchTransformer R4: split copy (cudaMemcpyAsync D2D, near-SOL HBM) from
// patch compositing (kernel over 8 per-patch 288x272 bounding regions only).
// Every region thread composites from clean through ALL 8 patches in order,
// so overlapping regions produce identical (idempotent) writes.
// Exact-fp replication of the reference grid_sample chain (rn intrinsics
// block FMA contraction) because the reference gates on mask == 1.0 and
// adv == 0.0 equality.

#define S 1024
#define PS 256
#define NPATCH 8
#define RGN_W 288   // 9 blocks * 32
#define RGN_H 272   // 34 blocks * 8

__global__ __launch_bounds__(256)
void patch_region_kernel(const float* __restrict__ patches,   // [8,3,256,256]
                         const float* __restrict__ locs,      // [8,2]
                         const float* __restrict__ clean,     // [3,1024,1024]
                         float* __restrict__ out)             // [3,1024,1024]
{
    __shared__ float sloc[2 * NPATCH];   // raw locations
    __shared__ float spx[NPATCH];        // 512 * lx
    __shared__ float spy[NPATCH];        // 512 * ly
    __shared__ int   sorg[2];            // region origin (w,h) for this blockIdx.z

    const int tid = threadIdx.y * 32 + threadIdx.x;
    if (tid < 2 * NPATCH) sloc[tid] = locs[tid];
    if (tid < NPATCH) {
        spx[tid] = 512.0f * locs[2 * tid + 0];
        spy[tid] = 512.0f * locs[2 * tid + 1];
    }
    if (tid == 16) {
        const int nr = blockIdx.z;
        sorg[0] = (int)floorf(512.0f * locs[2 * nr + 0]) - 4;
        sorg[1] = (int)floorf(512.0f * locs[2 * nr + 1]) - 4;
    }
    __syncthreads();

    const int w = sorg[0] + blockIdx.x * 32 + threadIdx.x;
    const int h = sorg[1] + blockIdx.y * 8  + threadIdx.y;
    if ((unsigned)w >= (unsigned)S || (unsigned)h >= (unsigned)S) return;

    const int pix = h * S + w;
    float v0 = clean[pix];
    float v1 = clean[pix + S * S];
    float v2 = clean[pix + 2 * S * S];

    const float wf = (float)w;
    const float hf = (float)h;

    // Normalized grid coords, exact reference chain (all steps exact fp32).
    const float gx = __fadd_rn(__fmul_rn(__fmul_rn(__fadd_rn(wf, 0.5f), 2.0f),
                                         (1.0f / 1024.0f)), -1.0f);
    const float gy = __fadd_rn(__fmul_rn(__fmul_rn(__fadd_rn(hf, 0.5f), 2.0f),
                                         (1.0f / 1024.0f)), -1.0f);

    #pragma unroll 1
    for (int n = 0; n < NPATCH; ++n) {
        // Cheap conservative bbox reject: exact x == w - 512*lx to within
        // ~0.01px; pixel participates only if x in [-1, 257).
        const float px = spx[n];
        const float py = spy[n];
        if (wf < px - 2.0f || wf > px + 258.0f ||
            hf < py - 2.0f || hf > py + 258.0f) continue;

        const float lx = sloc[2 * n + 0];
        const float ly = sloc[2 * n + 1];

        const float gry = __fadd_rn(gy, -ly);
        const float y = __fmul_rn(__fadd_rn(__fmul_rn(__fadd_rn(gry, 1.0f), 1024.0f), -1.0f), 0.5f);
        const float y0f = floorf(y);
        const int iy0 = (int)y0f;
        if ((unsigned)(iy0 + 1) > 256u) continue;

        const float grx = __fadd_rn(gx, -lx);
        const float x = __fmul_rn(__fadd_rn(__fmul_rn(__fadd_rn(grx, 1.0f), 1024.0f), -1.0f), 0.5f);
        const float x0f = floorf(x);
        const int ix0 = (int)x0f;
        if ((unsigned)(ix0 + 1) > 256u) continue;

        const float wx1 = __fadd_rn(x, -x0f);
        const float wx0 = __fadd_rn(1.0f, -wx1);
        const float wy1 = __fadd_rn(y, -y0f);
        const float wy0 = __fadd_rn(1.0f, -wy1);

        const float w00 = __fmul_rn(wy0, wx0);
        const float w01 = __fmul_rn(wy0, wx1);
        const float w10 = __fmul_rn(wy1, wx0);
        const float w11 = __fmul_rn(wy1, wx1);

        const bool vx0 = (ix0 >= 0);
        const bool vy0 = (iy0 >= 0);
        // mask_w = left-associated sum of valid*weight, exactly as reference.
        // (Inside the footprint, the +1 taps are always frame-valid.)
        const float m = __fadd_rn(__fadd_rn(__fadd_rn(
                            (vy0 && vx0) ? w00 : 0.0f,
                            vy0 ? w01 : 0.0f),
                            vx0 ? w10 : 0.0f),
                            w11);
        if (m != 1.0f) continue;

        const bool cx1 = (ix0 <= PS - 2);
        const bool cy1 = (iy0 <= PS - 2);
        const bool t00v = vy0 && vx0;
        const bool t01v = vy0 && cx1;
        const bool t10v = cy1 && vx0;
        const bool t11v = cy1 && cx1;
        if (!(t00v | t01v | t10v | t11v)) continue;

        const float* P = patches + (size_t)n * 3 * PS * PS;
        const int o00 = iy0 * PS + ix0;

        #pragma unroll
        for (int c = 0; c < 3; ++c) {
            const float* B = P + c * PS * PS;
            const float t00 = t00v ? __fmul_rn(__ldg(B + o00),          w00) : 0.0f;
            const float t01 = t01v ? __fmul_rn(__ldg(B + o00 + 1),      w01) : 0.0f;
            const float t10 = t10v ? __fmul_rn(__ldg(B + o00 + PS),     w10) : 0.0f;
            const float t11 = t11v ? __fmul_rn(__ldg(B + o00 + PS + 1), w11) : 0.0f;
            const float p = __fadd_rn(__fadd_rn(__fadd_rn(t00, t01), t10), t11);
            if (p != 0.0f) {
                if (c == 0) v0 = p;
                else if (c == 1) v1 = p;
                else v2 = p;
            }
        }
    }

    out[pix]             = v0;
    out[pix + S * S]     = v1;
    out[pix + 2 * S * S] = v2;
}

extern "C" void kernel_launch(void* const* d_in, const int* in_sizes, int n_in,
                              void* d_out, int out_size) {
    const float* patches = (const float*)d_in[0];   // (8,3,256,256)
    const float* locs    = (const float*)d_in[1];   // (8,2)
    const float* clean   = (const float*)d_in[2];   // (3,1024,1024)
    float* out = (float*)d_out;                     // (1,3,1024,1024)

    // 1) Bulk copy clean -> out (graph-legal async D2D memcpy node).
    cudaMemcpyAsync(out, clean, (size_t)3 * S * S * sizeof(float),
                    cudaMemcpyDeviceToDevice);

    // 2) Composite patches over their bounding regions only.
    dim3 block(32, 8);
    dim3 grid(RGN_W / 32, RGN_H / 8, NPATCH);   // 9 x 34 x 8 = 2448 blocks
    patch_region_kernel<<<grid, block>>>(patches, locs, clean, out);
}

// round 5
// speedup vs baseline: 1.1195x; 1.1195x over previous
#include <cuda_runtime.h>
#include <cstdint>

// PatchTransformer R5: single kernel, two write-disjoint block families run
// concurrently:
//  - region blocks: composite the 8 patch bounding boxes (write every
//    in-image bbox pixel: patched value or clean fallback)
//  - copy blocks: float4 copy of the exact complement (skip bbox pixels)
// No memcpy, no ordering. Overlapping regions double-write identical values.
// Exact-fp replication of the reference grid_sample chain (rn intrinsics
// block FMA contraction): reference gates on mask==1.0 and adv==0.0 equality.

#define S 1024
#define PS 256
#define NP 8
#define RW 288            // region width  = 9 * 32
#define RH 272            // region height = 34 * 8
#define RBX 9
#define RBY 34
#define NREG (RBX * RBY * NP)   // 2448
#define NCOPY ((S / 128) * (S / 8))  // 8 * 128 = 1024

__global__ __launch_bounds__(256, 8)
void patch_fused_kernel(const float* __restrict__ patches,   // [8,3,256,256]
                        const float* __restrict__ locs,      // [8,2]
                        const float* __restrict__ clean,     // [3,1024,1024]
                        float* __restrict__ out)             // [3,1024,1024]
{
    __shared__ float s_loc[2 * NP];
    __shared__ float s_px[NP], s_py[NP];
    __shared__ int   s_ox[NP], s_oy[NP];

    const int tid = threadIdx.y * 32 + threadIdx.x;
    if (tid < NP) {
        const float lx = locs[2 * tid], ly = locs[2 * tid + 1];
        s_px[tid] = 512.0f * lx;
        s_py[tid] = 512.0f * ly;
        s_ox[tid] = (int)floorf(512.0f * lx) - 4;
        s_oy[tid] = (int)floorf(512.0f * ly) - 4;
    }
    if (tid < 2 * NP) s_loc[tid] = locs[tid];
    __syncthreads();

    const int bid = blockIdx.x;

    if (bid < NREG) {
        // ---------------- region (composite) blocks ----------------
        const int n  = bid / (RBX * RBY);
        const int r  = bid - n * (RBX * RBY);
        const int by = r / RBX;
        const int bx = r - by * RBX;
        const int tw0 = s_ox[n] + bx * 32;
        const int th0 = s_oy[n] + by * 8;

        // Block-uniform candidate mask from tile bounds (conservative:
        // exact x == w - 512*lx to within ~0.01px; active iff x in [-1,257)).
        unsigned cmask = 0;
        #pragma unroll
        for (int m = 0; m < NP; ++m) {
            const bool ax = ((float)tw0        <= s_px[m] + 258.0f) &&
                            ((float)(tw0 + 31) >= s_px[m] - 2.0f);
            const bool ay = ((float)th0        <= s_py[m] + 258.0f) &&
                            ((float)(th0 + 7)  >= s_py[m] - 2.0f);
            if (ax && ay) cmask |= (1u << m);
        }

        const int w = tw0 + threadIdx.x;
        const int h = th0 + threadIdx.y;
        if ((unsigned)w >= (unsigned)S || (unsigned)h >= (unsigned)S) return;

        const int pix = h * S + w;
        float v0 = clean[pix];
        float v1 = clean[pix + S * S];
        float v2 = clean[pix + 2 * S * S];

        // Normalized grid coords, exact reference chain (all steps exact fp32).
        const float gx = __fadd_rn(__fmul_rn(__fmul_rn(__fadd_rn((float)w, 0.5f), 2.0f),
                                             (1.0f / 1024.0f)), -1.0f);
        const float gy = __fadd_rn(__fmul_rn(__fmul_rn(__fadd_rn((float)h, 0.5f), 2.0f),
                                             (1.0f / 1024.0f)), -1.0f);

        while (cmask) {
            const int m = __ffs(cmask) - 1;    // ascending = reference paste order
            cmask &= cmask - 1;

            const float lx = s_loc[2 * m + 0];
            const float ly = s_loc[2 * m + 1];

            const float gry = __fadd_rn(gy, -ly);
            const float y = __fmul_rn(__fadd_rn(__fmul_rn(__fadd_rn(gry, 1.0f), 1024.0f), -1.0f), 0.5f);
            const float y0f = floorf(y);
            const int iy0 = (int)y0f;
            if ((unsigned)(iy0 + 1) > 256u) continue;

            const float grx = __fadd_rn(gx, -lx);
            const float x = __fmul_rn(__fadd_rn(__fmul_rn(__fadd_rn(grx, 1.0f), 1024.0f), -1.0f), 0.5f);
            const float x0f = floorf(x);
            const int ix0 = (int)x0f;
            if ((unsigned)(ix0 + 1) > 256u) continue;

            const float wx1 = __fadd_rn(x, -x0f);
            const float wx0 = __fadd_rn(1.0f, -wx1);
            const float wy1 = __fadd_rn(y, -y0f);
            const float wy0 = __fadd_rn(1.0f, -wy1);

            const float w00 = __fmul_rn(wy0, wx0);
            const float w01 = __fmul_rn(wy0, wx1);
            const float w10 = __fmul_rn(wy1, wx0);
            const float w11 = __fmul_rn(wy1, wx1);

            const bool vx0 = (ix0 >= 0);
            const bool vy0 = (iy0 >= 0);
            // mask_w = left-associated sum of valid*weight, exactly as reference
            // (inside the footprint the +1 taps are always frame-valid).
            const float msum = __fadd_rn(__fadd_rn(__fadd_rn(
                                   (vy0 && vx0) ? w00 : 0.0f,
                                   vy0 ? w01 : 0.0f),
                                   vx0 ? w10 : 0.0f),
                                   w11);
            if (msum != 1.0f) continue;

            const bool cx1 = (ix0 <= PS - 2);
            const bool cy1 = (iy0 <= PS - 2);
            const bool t00v = vy0 && vx0;
            const bool t01v = vy0 && cx1;
            const bool t10v = cy1 && vx0;
            const bool t11v = cy1 && cx1;
            if (!(t00v | t01v | t10v | t11v)) continue;

            const float* P = patches + (size_t)m * 3 * PS * PS;
            const int o00 = iy0 * PS + ix0;

            #pragma unroll
            for (int c = 0; c < 3; ++c) {
                const float* B = P + c * PS * PS;
                const float t00 = t00v ? __fmul_rn(__ldg(B + o00),          w00) : 0.0f;
                const float t01 = t01v ? __fmul_rn(__ldg(B + o00 + 1),      w01) : 0.0f;
                const float t10 = t10v ? __fmul_rn(__ldg(B + o00 + PS),     w10) : 0.0f;
                const float t11 = t11v ? __fmul_rn(__ldg(B + o00 + PS + 1), w11) : 0.0f;
                const float p = __fadd_rn(__fadd_rn(__fadd_rn(t00, t01), t10), t11);
                if (p != 0.0f) {
                    if (c == 0) v0 = p;
                    else if (c == 1) v1 = p;
                    else v2 = p;
                }
            }
        }

        out[pix]             = v0;
        out[pix + S * S]     = v1;
        out[pix + 2 * S * S] = v2;

    } else {
        // ---------------- copy blocks (complement of all bboxes) ----------------
        const int c   = bid - NREG;
        const int by  = c >> 3;          // 128 rows of tiles (8 px tall)
        const int bx  = c & 7;           // 8 cols of tiles (128 px wide)
        const int tw0 = bx * 128;
        const int th0 = by * 8;

        // Block-uniform: which bboxes intersect this tile?
        unsigned imask = 0;
        #pragma unroll
        for (int m = 0; m < NP; ++m) {
            const bool ax = (tw0 < s_ox[m] + RW) && (tw0 + 127 >= s_ox[m]);
            const bool ay = (th0 < s_oy[m] + RH) && (th0 + 7   >= s_oy[m]);
            if (ax && ay) imask |= (1u << m);
        }

        const int w0  = tw0 + threadIdx.x * 4;
        const int h   = th0 + threadIdx.y;
        const int pix = h * S + w0;

        const float4 a0 = *(const float4*)(clean + pix);
        const float4 a1 = *(const float4*)(clean + pix + S * S);
        const float4 a2 = *(const float4*)(clean + pix + 2 * S * S);

        if (imask == 0) {
            *(float4*)(out + pix)             = a0;
            *(float4*)(out + pix + S * S)     = a1;
            *(float4*)(out + pix + 2 * S * S) = a2;
        } else {
            // Pixel-exact skip of bbox members (region blocks write those).
            unsigned keep = 0;   // bit k -> write pixel w0+k
            #pragma unroll
            for (int k = 0; k < 4; ++k) {
                bool inside = false;
                unsigned mm = imask;
                while (mm) {
                    const int m = __ffs(mm) - 1;
                    mm &= mm - 1;
                    const int wk = w0 + k;
                    if (wk >= s_ox[m] && wk < s_ox[m] + RW &&
                        h  >= s_oy[m] && h  < s_oy[m] + RH) { inside = true; break; }
                }
                if (!inside) keep |= (1u << k);
            }
            if (keep == 0xFu) {
                *(float4*)(out + pix)             = a0;
                *(float4*)(out + pix + S * S)     = a1;
                *(float4*)(out + pix + 2 * S * S) = a2;
            } else if (keep) {
                const float e0[4] = {a0.x, a0.y, a0.z, a0.w};
                const float e1[4] = {a1.x, a1.y, a1.z, a1.w};
                const float e2[4] = {a2.x, a2.y, a2.z, a2.w};
                #pragma unroll
                for (int k = 0; k < 4; ++k) {
                    if (keep & (1u << k)) {
                        out[pix + k]             = e0[k];
                        out[pix + k + S * S]     = e1[k];
                        out[pix + k + 2 * S * S] = e2[k];
                    }
                }
            }
        }
    }
}

extern "C" void kernel_launch(void* const* d_in, const int* in_sizes, int n_in,
                              void* d_out, int out_size) {
    const float* patches = (const float*)d_in[0];   // (8,3,256,256)
    const float* locs    = (const float*)d_in[1];   // (8,2)
    const float* clean   = (const float*)d_in[2];   // (3,1024,1024)
    float* out = (float*)d_out;                     // (1,3,1024,1024)

    dim3 block(32, 8);
    dim3 grid(NREG + NCOPY, 1, 1);   // 2448 region + 1024 copy = 3472 blocks
    patch_fused_kernel<<<grid, block>>>(patches, locs, clean, out);
}

// round 6
// speedup vs baseline: 1.2553x; 1.1213x over previous
#include <cuda_runtime.h>
#include <cstdint>

// PatchTransformer R6: dense balanced grid (R1 structure: 4096 blocks, 1 px/thread)
// + cheap conservative per-pixel bbox reject per patch (exact chain only for
// survivors, avg ~0.5 per pixel). Exact-fp replication of the reference
// grid_sample chain (rn intrinsics block FMA contraction) because the
// reference gates on mask == 1.0 and adv == 0.0 equality.

#define S 1024
#define PS 256
#define NP 8

__global__ __launch_bounds__(256, 8)
void patch_transformer_kernel(const float* __restrict__ patches,   // [8,3,256,256]
                              const float* __restrict__ locs,      // [8,2]
                              const float* __restrict__ clean,     // [3,1024,1024]
                              float* __restrict__ out)             // [3,1024,1024]
{
    __shared__ float s_loc[2 * NP];
    __shared__ float s_px[NP], s_py[NP];   // 512 * loc, for bbox tests

    const int tid = threadIdx.y * 32 + threadIdx.x;
    if (tid < 2 * NP) s_loc[tid] = locs[tid];
    if (tid < NP) {
        s_px[tid] = 512.0f * locs[2 * tid + 0];
        s_py[tid] = 512.0f * locs[2 * tid + 1];
    }
    __syncthreads();

    const int w = blockIdx.x * 32 + threadIdx.x;
    const int h = blockIdx.y * 8 + threadIdx.y;
    const int pix = h * S + w;

    float v0 = clean[pix];
    float v1 = clean[pix + S * S];
    float v2 = clean[pix + 2 * S * S];

    const float wf = (float)w;
    const float hf = (float)h;

    // Normalized grid coords, exact reference chain (all steps exact fp32).
    const float gx = __fadd_rn(__fmul_rn(__fmul_rn(__fadd_rn(wf, 0.5f), 2.0f),
                                         (1.0f / 1024.0f)), -1.0f);
    const float gy = __fadd_rn(__fmul_rn(__fmul_rn(__fadd_rn(hf, 0.5f), 2.0f),
                                         (1.0f / 1024.0f)), -1.0f);

    #pragma unroll 1
    for (int n = 0; n < NP; ++n) {
        // Conservative bbox reject: exact x equals (w - 512*lx) to within
        // <1e-3 px; the pixel can touch patch data only if x in [-1, 257).
        // +-2 px margin keeps this strictly conservative.
        const float px = s_px[n];
        const float py = s_py[n];
        if (wf < px - 2.0f || wf > px + 258.0f ||
            hf < py - 2.0f || hf > py + 258.0f) continue;

        const float lx = s_loc[2 * n + 0];
        const float ly = s_loc[2 * n + 1];

        // Exact reference chain (bit-for-bit).
        const float gry = __fadd_rn(gy, -ly);
        const float y = __fmul_rn(__fadd_rn(__fmul_rn(__fadd_rn(gry, 1.0f), 1024.0f), -1.0f), 0.5f);
        const float y0f = floorf(y);
        const int iy0 = (int)y0f;
        if ((unsigned)(iy0 + 1) > 256u) continue;

        const float grx = __fadd_rn(gx, -lx);
        const float x = __fmul_rn(__fadd_rn(__fmul_rn(__fadd_rn(grx, 1.0f), 1024.0f), -1.0f), 0.5f);
        const float x0f = floorf(x);
        const int ix0 = (int)x0f;
        if ((unsigned)(ix0 + 1) > 256u) continue;

        const float wx1 = __fadd_rn(x, -x0f);
        const float wx0 = __fadd_rn(1.0f, -wx1);
        const float wy1 = __fadd_rn(y, -y0f);
        const float wy0 = __fadd_rn(1.0f, -wy1);

        const float w00 = __fmul_rn(wy0, wx0);
        const float w01 = __fmul_rn(wy0, wx1);
        const float w10 = __fmul_rn(wy1, wx0);
        const float w11 = __fmul_rn(wy1, wx1);

        const bool vx0 = (ix0 >= 0);
        const bool vy0 = (iy0 >= 0);
        // mask_w = left-associated sum of valid*weight, exactly as reference
        // (inside the footprint the +1 taps are always frame-valid).
        const float msum = __fadd_rn(__fadd_rn(__fadd_rn(
                               (vy0 && vx0) ? w00 : 0.0f,
                               vy0 ? w01 : 0.0f),
                               vx0 ? w10 : 0.0f),
                               w11);
        if (msum != 1.0f) continue;

        const bool cx1 = (ix0 <= PS - 2);
        const bool cy1 = (iy0 <= PS - 2);
        const bool t00v = vy0 && vx0;
        const bool t01v = vy0 && cx1;
        const bool t10v = cy1 && vx0;
        const bool t11v = cy1 && cx1;
        if (!(t00v | t01v | t10v | t11v)) continue;

        const float* P = patches + (size_t)n * 3 * PS * PS;
        const int o00 = iy0 * PS + ix0;

        #pragma unroll
        for (int c = 0; c < 3; ++c) {
            const float* B = P + c * PS * PS;
            const float t00 = t00v ? __fmul_rn(__ldg(B + o00),          w00) : 0.0f;
            const float t01 = t01v ? __fmul_rn(__ldg(B + o00 + 1),      w01) : 0.0f;
            const float t10 = t10v ? __fmul_rn(__ldg(B + o00 + PS),     w10) : 0.0f;
            const float t11 = t11v ? __fmul_rn(__ldg(B + o00 + PS + 1), w11) : 0.0f;
            const float p = __fadd_rn(__fadd_rn(__fadd_rn(t00, t01), t10), t11);
            if (p != 0.0f) {
                if (c == 0) v0 = p;
                else if (c == 1) v1 = p;
                else v2 = p;
            }
        }
    }

    out[pix]             = v0;
    out[pix + S * S]     = v1;
    out[pix + 2 * S * S] = v2;
}

extern "C" void kernel_launch(void* const* d_in, const int* in_sizes, int n_in,
                              void* d_out, int out_size) {
    const float* patches = (const float*)d_in[0];   // (8,3,256,256)
    const float* locs    = (const float*)d_in[1];   // (8,2)
    const float* clean   = (const float*)d_in[2];   // (3,1024,1024)
    float* out = (float*)d_out;                     // (1,3,1024,1024)

    dim3 block(32, 8);
    dim3 grid(S / 32, S / 8);   // 32 x 128 = 4096 blocks, 1 px/thread
    patch_transformer_kernel<<<grid, block>>>(patches, locs, clean, out);
}

// round 7
// speedup vs baseline: 1.4496x; 1.1548x over previous
#include <cuda_runtime.h>
#include <cstdint>

// PatchTransformer R7: single-wave execution (1024 blocks x 2 tiles each, all
// resident at 8 CTA/SM), 2px/thread float2, block-uniform per-tile patch mask
// built by warp0 ballot (no per-pixel patch loop on copy-only tiles).
// Exact-fp replication of the reference grid_sample chain (rn intrinsics
// block FMA contraction): reference gates on mask==1.0 and adv==0.0 equality.

#define S 1024
#define PS 256
#define NP 8
#define NBLK 1024         // single wave: <= 1184 concurrent CTAs at 8/SM
#define TILES 2048        // 16 cols (64px) x 128 rows (8px)

__global__ __launch_bounds__(256, 8)
void patch_transformer_kernel(const float* __restrict__ patches,   // [8,3,256,256]
                              const float* __restrict__ locs,      // [8,2]
                              const float* __restrict__ clean,     // [3,1024,1024]
                              float* __restrict__ out)             // [3,1024,1024]
{
    __shared__ float s_loc[2 * NP];
    __shared__ float s_px[NP], s_py[NP];
    __shared__ unsigned s_mask[2];       // per-tile candidate patch mask

    const int tid = threadIdx.y * 32 + threadIdx.x;
    if (tid < 2 * NP) s_loc[tid] = locs[tid];
    if (tid < NP) {
        s_px[tid] = 512.0f * locs[2 * tid + 0];
        s_py[tid] = 512.0f * locs[2 * tid + 1];
    }
    __syncthreads();

    // Warp 0 builds both tiles' candidate masks with one ballot.
    // Conservative: exact x == w - 512*lx to within <1e-3 px; a pixel can
    // touch patch data only if x in [-1,257). +-2px margin.
    if (tid < 32) {
        bool hit = false;
        if (tid < 2 * NP) {
            const int t   = (tid < NP) ? blockIdx.x : blockIdx.x + NBLK;
            const int m   = (tid < NP) ? tid : tid - NP;
            const int tw0 = (t & 15) * 64;
            const int th0 = (t >> 4) * 8;
            hit = ((float)tw0        <= s_px[m] + 258.0f) &&
                  ((float)(tw0 + 63) >= s_px[m] - 2.0f)   &&
                  ((float)th0        <= s_py[m] + 258.0f) &&
                  ((float)(th0 + 7)  >= s_py[m] - 2.0f);
        }
        const unsigned bal = __ballot_sync(0xFFFFFFFFu, hit);
        if (tid == 0) {
            s_mask[0] = bal & 0xFFu;
            s_mask[1] = (bal >> NP) & 0xFFu;
        }
    }
    __syncthreads();

    #pragma unroll
    for (int ti = 0; ti < 2; ++ti) {
        const int t   = blockIdx.x + ti * NBLK;
        const int w0  = (t & 15) * 64 + threadIdx.x * 2;
        const int h   = (t >> 4) * 8 + threadIdx.y;
        const int pix = h * S + w0;

        float2 a0 = *(const float2*)(clean + pix);
        float2 a1 = *(const float2*)(clean + pix + S * S);
        float2 a2 = *(const float2*)(clean + pix + 2 * S * S);

        unsigned cmask = s_mask[ti];
        if (cmask) {
            float v[3][2] = {{a0.x, a0.y}, {a1.x, a1.y}, {a2.x, a2.y}};

            // Normalized grid coords, exact reference chain (all exact fp32).
            const float gy = __fadd_rn(__fmul_rn(__fmul_rn(__fadd_rn((float)h, 0.5f), 2.0f),
                                                 (1.0f / 1024.0f)), -1.0f);
            float gxk[2];
            #pragma unroll
            for (int k = 0; k < 2; ++k)
                gxk[k] = __fadd_rn(__fmul_rn(__fmul_rn(__fadd_rn((float)(w0 + k), 0.5f), 2.0f),
                                             (1.0f / 1024.0f)), -1.0f);

            do {
                const int n = __ffs(cmask) - 1;   // ascending = reference paste order
                cmask &= cmask - 1;

                const float lx = s_loc[2 * n + 0];
                const float ly = s_loc[2 * n + 1];

                // y chain shared by the thread's 2 pixels (same h).
                const float gry = __fadd_rn(gy, -ly);
                const float y = __fmul_rn(__fadd_rn(__fmul_rn(__fadd_rn(gry, 1.0f), 1024.0f), -1.0f), 0.5f);
                const float y0f = floorf(y);
                const int iy0 = (int)y0f;
                if ((unsigned)(iy0 + 1) > 256u) continue;

                const float wy1 = __fadd_rn(y, -y0f);
                const float wy0 = __fadd_rn(1.0f, -wy1);
                const bool vy0 = (iy0 >= 0);
                const bool cy1 = (iy0 <= PS - 2);

                const float* P = patches + (size_t)n * 3 * PS * PS;
                const int rowoff = iy0 * PS;

                #pragma unroll
                for (int k = 0; k < 2; ++k) {
                    const float grx = __fadd_rn(gxk[k], -lx);
                    const float x = __fmul_rn(__fadd_rn(__fmul_rn(__fadd_rn(grx, 1.0f), 1024.0f), -1.0f), 0.5f);
                    const float x0f = floorf(x);
                    const int ix0 = (int)x0f;
                    if ((unsigned)(ix0 + 1) > 256u) continue;

                    const float wx1 = __fadd_rn(x, -x0f);
                    const float wx0 = __fadd_rn(1.0f, -wx1);

                    const float w00 = __fmul_rn(wy0, wx0);
                    const float w01 = __fmul_rn(wy0, wx1);
                    const float w10 = __fmul_rn(wy1, wx0);
                    const float w11 = __fmul_rn(wy1, wx1);

                    const bool vx0 = (ix0 >= 0);
                    // mask_w = left-associated sum of valid*weight, exactly as
                    // reference (+1 taps always frame-valid inside footprint).
                    const float msum = __fadd_rn(__fadd_rn(__fadd_rn(
                                           (vy0 && vx0) ? w00 : 0.0f,
                                           vy0 ? w01 : 0.0f),
                                           vx0 ? w10 : 0.0f),
                                           w11);
                    if (msum != 1.0f) continue;

                    const bool cx1 = (ix0 <= PS - 2);
                    const bool t00v = vy0 && vx0;
                    const bool t01v = vy0 && cx1;
                    const bool t10v = cy1 && vx0;
                    const bool t11v = cy1 && cx1;
                    if (!(t00v | t01v | t10v | t11v)) continue;

                    const int o00 = rowoff + ix0;
                    #pragma unroll
                    for (int c = 0; c < 3; ++c) {
                        const float* B = P + c * PS * PS;
                        const float t00 = t00v ? __fmul_rn(__ldg(B + o00),          w00) : 0.0f;
                        const float t01 = t01v ? __fmul_rn(__ldg(B + o00 + 1),      w01) : 0.0f;
                        const float t10 = t10v ? __fmul_rn(__ldg(B + o00 + PS),     w10) : 0.0f;
                        const float t11 = t11v ? __fmul_rn(__ldg(B + o00 + PS + 1), w11) : 0.0f;
                        const float p = __fadd_rn(__fadd_rn(__fadd_rn(t00, t01), t10), t11);
                        if (p != 0.0f) v[c][k] = p;
                    }
                }
            } while (cmask);

            a0 = make_float2(v[0][0], v[0][1]);
            a1 = make_float2(v[1][0], v[1][1]);
            a2 = make_float2(v[2][0], v[2][1]);
        }

        *(float2*)(out + pix)             = a0;
        *(float2*)(out + pix + S * S)     = a1;
        *(float2*)(out + pix + 2 * S * S) = a2;
    }
}

extern "C" void kernel_launch(void* const* d_in, const int* in_sizes, int n_in,
                              void* d_out, int out_size) {
    const float* patches = (const float*)d_in[0];   // (8,3,256,256)
    const float* locs    = (const float*)d_in[1];   // (8,2)
    const float* clean   = (const float*)d_in[2];   // (3,1024,1024)
    float* out = (float*)d_out;                     // (1,3,1024,1024)

    dim3 block(32, 8);
    patch_transformer_kernel<<<NBLK, block>>>(patches, locs, clean, out);
}

// round 8
// speedup vs baseline: 1.7251x; 1.1901x over previous
#include <cuda_runtime.h>
#include <cstdint>

// PatchTransformer R8: R6's proven dense config (4096 blocks, 32x8, 1px/thread,
// 3.46 balanced waves, occ ~85%) with the per-pixel 8-iteration patch loop
// replaced by a block-uniform candidate mask (one ballot in warp 0). Copy-only
// blocks skip patch logic entirely. Exact-fp replication of the reference
// grid_sample chain (rn intrinsics block FMA contraction): reference gates on
// mask==1.0 and adv==0.0 equality.

#define S 1024
#define PS 256
#define NP 8

__global__ __launch_bounds__(256, 8)
void patch_transformer_kernel(const float* __restrict__ patches,   // [8,3,256,256]
                              const float* __restrict__ locs,      // [8,2]
                              const float* __restrict__ clean,     // [3,1024,1024]
                              float* __restrict__ out)             // [3,1024,1024]
{
    __shared__ float s_loc[2 * NP];
    __shared__ unsigned s_cmask;

    const int tid = threadIdx.y * 32 + threadIdx.x;
    if (tid < 2 * NP) s_loc[tid] = locs[tid];

    const int bw0 = blockIdx.x * 32;
    const int bh0 = blockIdx.y * 8;

    // Warp 0: block-uniform candidate mask. Conservative: exact sample coord
    // x == w - 512*lx to within <1e-3 px; a pixel can touch patch data only
    // if x in [-1,257). +-2 px margin keeps it strictly conservative.
    if (tid < 32) {
        bool hit = false;
        if (tid < NP) {
            const float px = 512.0f * __ldg(locs + 2 * tid + 0);
            const float py = 512.0f * __ldg(locs + 2 * tid + 1);
            hit = ((float)bw0        <= px + 258.0f) &&
                  ((float)(bw0 + 31) >= px - 2.0f)   &&
                  ((float)bh0        <= py + 258.0f) &&
                  ((float)(bh0 + 7)  >= py - 2.0f);
        }
        const unsigned bal = __ballot_sync(0xFFFFFFFFu, hit);
        if (tid == 0) s_cmask = bal & 0xFFu;
    }
    __syncthreads();

    const int w = bw0 + threadIdx.x;
    const int h = bh0 + threadIdx.y;
    const int pix = h * S + w;

    float v0 = clean[pix];
    float v1 = clean[pix + S * S];
    float v2 = clean[pix + 2 * S * S];

    unsigned cmask = s_cmask;
    if (cmask) {
        // Normalized grid coords, exact reference chain (all steps exact fp32).
        const float gx = __fadd_rn(__fmul_rn(__fmul_rn(__fadd_rn((float)w, 0.5f), 2.0f),
                                             (1.0f / 1024.0f)), -1.0f);
        const float gy = __fadd_rn(__fmul_rn(__fmul_rn(__fadd_rn((float)h, 0.5f), 2.0f),
                                             (1.0f / 1024.0f)), -1.0f);

        do {
            const int n = __ffs(cmask) - 1;   // ascending = reference paste order
            cmask &= cmask - 1;

            const float lx = s_loc[2 * n + 0];
            const float ly = s_loc[2 * n + 1];

            // Exact reference chain (bit-for-bit).
            const float gry = __fadd_rn(gy, -ly);
            const float y = __fmul_rn(__fadd_rn(__fmul_rn(__fadd_rn(gry, 1.0f), 1024.0f), -1.0f), 0.5f);
            const float y0f = floorf(y);
            const int iy0 = (int)y0f;
            if ((unsigned)(iy0 + 1) > 256u) continue;

            const float grx = __fadd_rn(gx, -lx);
            const float x = __fmul_rn(__fadd_rn(__fmul_rn(__fadd_rn(grx, 1.0f), 1024.0f), -1.0f), 0.5f);
            const float x0f = floorf(x);
            const int ix0 = (int)x0f;
            if ((unsigned)(ix0 + 1) > 256u) continue;

            const float wx1 = __fadd_rn(x, -x0f);
            const float wx0 = __fadd_rn(1.0f, -wx1);
            const float wy1 = __fadd_rn(y, -y0f);
            const float wy0 = __fadd_rn(1.0f, -wy1);

            const float w00 = __fmul_rn(wy0, wx0);
            const float w01 = __fmul_rn(wy0, wx1);
            const float w10 = __fmul_rn(wy1, wx0);
            const float w11 = __fmul_rn(wy1, wx1);

            const bool vx0 = (ix0 >= 0);
            const bool vy0 = (iy0 >= 0);
            // mask_w = left-associated sum of valid*weight, exactly as reference
            // (inside the footprint the +1 taps are always frame-valid).
            const float msum = __fadd_rn(__fadd_rn(__fadd_rn(
                                   (vy0 && vx0) ? w00 : 0.0f,
                                   vy0 ? w01 : 0.0f),
                                   vx0 ? w10 : 0.0f),
                                   w11);
            if (msum != 1.0f) continue;

            const bool cx1 = (ix0 <= PS - 2);
            const bool cy1 = (iy0 <= PS - 2);
            const bool t00v = vy0 && vx0;
            const bool t01v = vy0 && cx1;
            const bool t10v = cy1 && vx0;
            const bool t11v = cy1 && cx1;
            if (!(t00v | t01v | t10v | t11v)) continue;

            const float* P = patches + (size_t)n * 3 * PS * PS;
            const int o00 = iy0 * PS + ix0;

            #pragma unroll
            for (int c = 0; c < 3; ++c) {
                const float* B = P + c * PS * PS;
                const float t00 = t00v ? __fmul_rn(__ldg(B + o00),          w00) : 0.0f;
                const float t01 = t01v ? __fmul_rn(__ldg(B + o00 + 1),      w01) : 0.0f;
                const float t10 = t10v ? __fmul_rn(__ldg(B + o00 + PS),     w10) : 0.0f;
                const float t11 = t11v ? __fmul_rn(__ldg(B + o00 + PS + 1), w11) : 0.0f;
                const float p = __fadd_rn(__fadd_rn(__fadd_rn(t00, t01), t10), t11);
                if (p != 0.0f) {
                    if (c == 0) v0 = p;
                    else if (c == 1) v1 = p;
                    else v2 = p;
                }
            }
        } while (cmask);
    }

    out[pix]             = v0;
    out[pix + S * S]     = v1;
    out[pix + 2 * S * S] = v2;
}

extern "C" void kernel_launch(void* const* d_in, const int* in_sizes, int n_in,
                              void* d_out, int out_size) {
    const float* patches = (const float*)d_in[0];   // (8,3,256,256)
    const float* locs    = (const float*)d_in[1];   // (8,2)
    const float* clean   = (const float*)d_in[2];   // (3,1024,1024)
    float* out = (float*)d_out;                     // (1,3,1024,1024)

    dim3 block(32, 8);
    dim3 grid(S / 32, S / 8);   // 32 x 128 = 4096 blocks, 1 px/thread
    patch_transformer_kernel<<<grid, block>>>(patches, locs, clean, out);
}